// round 1
// baseline (speedup 1.0000x reference)
#include <cuda_runtime.h>
#include <cstdint>

#define NN   50000
#define EE   1600000
#define FIN  64
#define FOUT 64
#define KP   25
#define KROW (KP * FOUT)   // 1600 floats per node row in xw

// Scratch (device globals; no runtime allocation allowed)
__device__ float g_xw[(size_t)NN * KP * FOUT];  // 320 MB: xw[n][k][o]
__device__ float g_deg[NN];

// ---------------------------------------------------------------------------
// Kernel 1: zero output accumulator + degree counters
// ---------------------------------------------------------------------------
__global__ void zero_kernel(float* __restrict__ out) {
    int i = blockIdx.x * blockDim.x + threadIdx.x;
    if (i < NN * FOUT) out[i] = 0.0f;
    if (i < NN)        g_deg[i] = 0.0f;
}

// ---------------------------------------------------------------------------
// Kernel 2: xw[n,k,:] = x[n,:] @ W[k,:,:]
// Block: 128 nodes x one k. 256 threads, each computes 4 nodes x 8 outputs.
// ---------------------------------------------------------------------------
__global__ __launch_bounds__(256) void xw_gemm(const float* __restrict__ x,
                                               const float* __restrict__ w) {
    __shared__ float As[64][128];  // As[i][n_local]  (transposed x tile)
    __shared__ float Ws[64][64];   // Ws[i][o]
    const int k   = blockIdx.y;
    const int n0  = blockIdx.x * 128;
    const int tid = threadIdx.x;

    // Load W[k] (4096 floats, coalesced)
    {
        const float4* src = (const float4*)(w + (size_t)k * 4096);
        float4* dst = (float4*)(&Ws[0][0]);
        #pragma unroll
        for (int j = 0; j < 4; j++) dst[j * 256 + tid] = src[j * 256 + tid];
    }
    // Load x tile transposed: 128 nodes x 16 float4
    #pragma unroll
    for (int it = 0; it < 8; it++) {
        int flat = it * 256 + tid;
        int n  = flat & 127;   // consecutive lanes -> consecutive n (conflict-free STS)
        int i4 = flat >> 7;
        float4 v = make_float4(0.f, 0.f, 0.f, 0.f);
        int gn = n0 + n;
        if (gn < NN) v = *(const float4*)(x + (size_t)gn * FIN + i4 * 4);
        As[i4 * 4 + 0][n] = v.x;
        As[i4 * 4 + 1][n] = v.y;
        As[i4 * 4 + 2][n] = v.z;
        As[i4 * 4 + 3][n] = v.w;
    }
    __syncthreads();

    const int tx = tid & 7;    // 8 output columns (x8)
    const int ty = tid >> 3;   // 32 node groups (x4)
    float acc[4][8];
    #pragma unroll
    for (int m = 0; m < 4; m++)
        #pragma unroll
        for (int o = 0; o < 8; o++) acc[m][o] = 0.f;

    #pragma unroll 8
    for (int kk = 0; kk < 64; kk++) {
        float4 a  = *(const float4*)(&As[kk][ty * 4]);
        float4 b0 = *(const float4*)(&Ws[kk][tx * 8]);
        float4 b1 = *(const float4*)(&Ws[kk][tx * 8 + 4]);
        float av[4] = {a.x, a.y, a.z, a.w};
        float bv[8] = {b0.x, b0.y, b0.z, b0.w, b1.x, b1.y, b1.z, b1.w};
        #pragma unroll
        for (int m = 0; m < 4; m++)
            #pragma unroll
            for (int o = 0; o < 8; o++)
                acc[m][o] = fmaf(av[m], bv[o], acc[m][o]);
    }

    #pragma unroll
    for (int m = 0; m < 4; m++) {
        int gn = n0 + ty * 4 + m;
        if (gn < NN) {
            float* dst = g_xw + (size_t)gn * KROW + k * 64 + tx * 8;
            *(float4*)(dst)     = make_float4(acc[m][0], acc[m][1], acc[m][2], acc[m][3]);
            *(float4*)(dst + 4) = make_float4(acc[m][4], acc[m][5], acc[m][6], acc[m][7]);
        }
    }
}

// ---------------------------------------------------------------------------
// Kernel 3: per-edge gather + basis blend + scatter-add into out[row]
// One warp per edge; lane l handles outputs {2l, 2l+1}.
// ---------------------------------------------------------------------------
__global__ __launch_bounds__(256) void edge_kernel(const int*   __restrict__ ei,
                                                   const float* __restrict__ pseudo,
                                                   float*       __restrict__ out) {
    const int warp   = (blockIdx.x * blockDim.x + threadIdx.x) >> 5;
    const int lane   = threadIdx.x & 31;
    const int nwarps = (gridDim.x * blockDim.x) >> 5;

    for (int e = warp; e < EE; e += nwarps) {
        int row = ei[e];
        int col = ei[EE + e];
        float v0 = pseudo[2 * e]     * 4.0f;   // (K-1) scaling, K=5
        float v1 = pseudo[2 * e + 1] * 4.0f;
        float fl0 = floorf(v0), fl1 = floorf(v1);
        float f0 = v0 - fl0, f1 = v1 - fl1;
        int i0 = (int)fl0, i1 = (int)fl1;
        int i0p = i0 + 1; if (i0p >= 5) i0p -= 5;   // wrap (basis=0 there anyway)
        int i1p = i1 + 1; if (i1p >= 5) i1p -= 5;

        float g0 = 1.0f - f0, g1 = 1.0f - f1;
        float w00 = g0 * g1;   // (i0 , i1 )
        float w10 = f0 * g1;   // (i0p, i1 )
        float w01 = g0 * f1;   // (i0 , i1p)
        float w11 = f0 * f1;   // (i0p, i1p)

        const float* base = g_xw + (size_t)col * KROW;
        int o = lane * 2;
        float2 a = *(const float2*)(base + (i0  * 5 + i1 ) * 64 + o);
        float2 b = *(const float2*)(base + (i0p * 5 + i1 ) * 64 + o);
        float2 c = *(const float2*)(base + (i0  * 5 + i1p) * 64 + o);
        float2 d = *(const float2*)(base + (i0p * 5 + i1p) * 64 + o);

        float rx = w00 * a.x + w10 * b.x + w01 * c.x + w11 * d.x;
        float ry = w00 * a.y + w10 * b.y + w01 * c.y + w11 * d.y;

        float* op = out + (size_t)row * FOUT + o;
        asm volatile("red.global.add.v2.f32 [%0], {%1, %2};"
                     :: "l"(op), "f"(rx), "f"(ry) : "memory");
        if (lane == 0) atomicAdd(&g_deg[row], 1.0f);
    }
}

// ---------------------------------------------------------------------------
// Kernel 4: out = out / max(deg,1) + x @ root_weight + bias
// Same tiling as xw_gemm (128 nodes/block).
// ---------------------------------------------------------------------------
__global__ __launch_bounds__(256) void final_kernel(const float* __restrict__ x,
                                                    const float* __restrict__ root,
                                                    const float* __restrict__ bias,
                                                    float*       __restrict__ out) {
    __shared__ float As[64][128];
    __shared__ float Rs[64][64];
    const int n0  = blockIdx.x * 128;
    const int tid = threadIdx.x;

    {
        const float4* src = (const float4*)root;
        float4* dst = (float4*)(&Rs[0][0]);
        #pragma unroll
        for (int j = 0; j < 4; j++) dst[j * 256 + tid] = src[j * 256 + tid];
    }
    #pragma unroll
    for (int it = 0; it < 8; it++) {
        int flat = it * 256 + tid;
        int n  = flat & 127;
        int i4 = flat >> 7;
        float4 v = make_float4(0.f, 0.f, 0.f, 0.f);
        int gn = n0 + n;
        if (gn < NN) v = *(const float4*)(x + (size_t)gn * FIN + i4 * 4);
        As[i4 * 4 + 0][n] = v.x;
        As[i4 * 4 + 1][n] = v.y;
        As[i4 * 4 + 2][n] = v.z;
        As[i4 * 4 + 3][n] = v.w;
    }
    __syncthreads();

    const int tx = tid & 7;
    const int ty = tid >> 3;
    float acc[4][8];
    #pragma unroll
    for (int m = 0; m < 4; m++)
        #pragma unroll
        for (int o = 0; o < 8; o++) acc[m][o] = 0.f;

    #pragma unroll 8
    for (int kk = 0; kk < 64; kk++) {
        float4 a  = *(const float4*)(&As[kk][ty * 4]);
        float4 b0 = *(const float4*)(&Rs[kk][tx * 8]);
        float4 b1 = *(const float4*)(&Rs[kk][tx * 8 + 4]);
        float av[4] = {a.x, a.y, a.z, a.w};
        float bv[8] = {b0.x, b0.y, b0.z, b0.w, b1.x, b1.y, b1.z, b1.w};
        #pragma unroll
        for (int m = 0; m < 4; m++)
            #pragma unroll
            for (int o = 0; o < 8; o++)
                acc[m][o] = fmaf(av[m], bv[o], acc[m][o]);
    }

    #pragma unroll
    for (int m = 0; m < 4; m++) {
        int gn = n0 + ty * 4 + m;
        if (gn < NN) {
            float scale = 1.0f / fmaxf(g_deg[gn], 1.0f);
            float* dst = out + (size_t)gn * FOUT + tx * 8;
            #pragma unroll
            for (int o = 0; o < 8; o++) {
                dst[o] = dst[o] * scale + acc[m][o] + __ldg(bias + tx * 8 + o);
            }
        }
    }
}

// ---------------------------------------------------------------------------
extern "C" void kernel_launch(void* const* d_in, const int* in_sizes, int n_in,
                              void* d_out, int out_size) {
    const float* x      = (const float*)d_in[0];  // [N, 64]
    const int*   ei     = (const int*)  d_in[1];  // [2, E]
    const float* pseudo = (const float*)d_in[2];  // [E, 2]
    const float* weight = (const float*)d_in[3];  // [25, 64, 64]
    const float* root   = (const float*)d_in[4];  // [64, 64]
    const float* bias   = (const float*)d_in[5];  // [64]
    float* out = (float*)d_out;                   // [N, 64]

    // 1. zero out-accumulator and degree
    zero_kernel<<<(NN * FOUT + 255) / 256, 256>>>(out);

    // 2. xw = x @ W[k] for all k
    dim3 g2((NN + 127) / 128, KP);
    xw_gemm<<<g2, 256>>>(x, weight);

    // 3. edge scatter
    edge_kernel<<<4096, 256>>>(ei, pseudo, out);

    // 4. normalize + root term + bias
    final_kernel<<<(NN + 127) / 128, 256>>>(x, root, bias, out);
}

// round 3
// speedup vs baseline: 1.9838x; 1.9838x over previous
#include <cuda_runtime.h>
#include <cuda_bf16.h>
#include <cuda_fp16.h>
#include <cstdint>

#define NN   50000
#define EE   1600000
#define KP   25
#define FOUT 64
#define KROW (KP * FOUT)          // 1600

// ---------------- device scratch (no runtime allocation allowed) -----------
__device__ __nv_bfloat16 g_xhi[(size_t)NN * 64];
__device__ __nv_bfloat16 g_xlo[(size_t)NN * 64];
__device__ __nv_bfloat16 g_wthi[KP * 64 * 64];   // W^T: [k][o][i]
__device__ __nv_bfloat16 g_wtlo[KP * 64 * 64];
__device__ __half        g_xw[(size_t)NN * KROW];   // 160 MB fp16 table
__device__ float         g_deg[NN];

// ---------------- helpers ---------------------------------------------------
__device__ __forceinline__ uint32_t smem_u32(const void* p) {
    uint32_t a;
    asm("{ .reg .u64 t; cvta.to.shared.u64 t, %1; cvt.u32.u64 %0, t; }"
        : "=r"(a) : "l"(p));
    return a;
}
__device__ __forceinline__ void ldsm_x4(uint32_t addr, uint32_t* r) {
    asm volatile("ldmatrix.sync.aligned.m8n8.x4.shared.b16 {%0,%1,%2,%3}, [%4];"
                 : "=r"(r[0]), "=r"(r[1]), "=r"(r[2]), "=r"(r[3]) : "r"(addr));
}
__device__ __forceinline__ void ldsm_x2(uint32_t addr, uint32_t* r) {
    asm volatile("ldmatrix.sync.aligned.m8n8.x2.shared.b16 {%0,%1}, [%2];"
                 : "=r"(r[0]), "=r"(r[1]) : "r"(addr));
}
__device__ __forceinline__ void mma_bf16(float* c, const uint32_t* a, const uint32_t* b) {
    asm volatile(
        "mma.sync.aligned.m16n8k16.row.col.f32.bf16.bf16.f32 "
        "{%0,%1,%2,%3}, {%4,%5,%6,%7}, {%8,%9}, {%0,%1,%2,%3};"
        : "+f"(c[0]), "+f"(c[1]), "+f"(c[2]), "+f"(c[3])
        : "r"(a[0]), "r"(a[1]), "r"(a[2]), "r"(a[3]), "r"(b[0]), "r"(b[1]));
}

// ---------------------------------------------------------------------------
// prep: split x and W^T into bf16 hi/lo
// ---------------------------------------------------------------------------
__global__ void prep_x(const float* __restrict__ x) {
    int i = blockIdx.x * blockDim.x + threadIdx.x;
    if (i >= NN * 64) return;
    float v = x[i];
    __nv_bfloat16 h = __float2bfloat16(v);
    g_xhi[i] = h;
    g_xlo[i] = __float2bfloat16(v - __bfloat162float(h));
}
__global__ void prep_w(const float* __restrict__ w) {
    int i = blockIdx.x * blockDim.x + threadIdx.x;
    if (i >= KP * 64 * 64) return;
    int k = i >> 12, rem = i & 4095;
    int ii = rem >> 6, o = rem & 63;
    float v = w[i];
    __nv_bfloat16 h = __float2bfloat16(v);
    int dst = (k << 12) + (o << 6) + ii;     // [k][o][i]
    g_wthi[dst] = h;
    g_wtlo[dst] = __float2bfloat16(v - __bfloat162float(h));
}
__global__ void zero_kernel(float* __restrict__ out) {
    int i = blockIdx.x * blockDim.x + threadIdx.x;
    if (i < NN * FOUT) out[i] = 0.0f;
    if (i < NN)        g_deg[i] = 0.0f;
}

// ---------------------------------------------------------------------------
// xw[n,k,:] = x[n,:] @ W[k]  via mma.sync bf16 hi/lo split (3 passes)
// Block: 256 threads (8 warps), 128 nodes x one k. Warp w: rows w*16..w*16+15.
// ---------------------------------------------------------------------------
#define PADR 72   // row pad (bf16 elems): 144 B rows -> LDSM conflict-free

__global__ __launch_bounds__(256) void xw_mma(float* /*unused*/) {
    extern __shared__ __nv_bfloat16 sm[];
    __nv_bfloat16* xh = sm;                       // [128][PADR]
    __nv_bfloat16* xl = xh + 128 * PADR;
    __nv_bfloat16* wh = xl + 128 * PADR;          // [64][PADR]
    __nv_bfloat16* wl = wh + 64 * PADR;

    const int tid  = threadIdx.x;
    const int wid  = tid >> 5;
    const int lane = tid & 31;
    const int k    = blockIdx.y;
    const int n0   = blockIdx.x * 128;

    // load x tile hi/lo (128 rows x 64 bf16 = 8 uint4/row)
    #pragma unroll
    for (int it = 0; it < 4; it++) {
        int flat = tid + 256 * it;
        int r = flat >> 3, j = flat & 7;
        int gn = n0 + r;
        uint4 vh = make_uint4(0, 0, 0, 0), vl = vh;
        if (gn < NN) {
            vh = *(const uint4*)(g_xhi + (size_t)gn * 64 + j * 8);
            vl = *(const uint4*)(g_xlo + (size_t)gn * 64 + j * 8);
        }
        *(uint4*)(xh + r * PADR + j * 8) = vh;
        *(uint4*)(xl + r * PADR + j * 8) = vl;
    }
    // load W^T[k] hi/lo (64 rows x 64 bf16)
    #pragma unroll
    for (int it = 0; it < 2; it++) {
        int flat = tid + 256 * it;
        int r = flat >> 3, j = flat & 7;
        uint4 vh = *(const uint4*)(g_wthi + (k << 12) + r * 64 + j * 8);
        uint4 vl = *(const uint4*)(g_wtlo + (k << 12) + r * 64 + j * 8);
        *(uint4*)(wh + r * PADR + j * 8) = vh;
        *(uint4*)(wl + r * PADR + j * 8) = vl;
    }
    __syncthreads();

    const int m0 = wid * 16;
    float acc[8][4];
    #pragma unroll
    for (int nt = 0; nt < 8; nt++)
        #pragma unroll
        for (int q = 0; q < 4; q++) acc[nt][q] = 0.f;

    // A ldsm address: lanes 0-15 rows, 16-31 same rows col+8
    const int a_row = m0 + (lane & 15);
    const int a_c8  = (lane >> 4) * 8;
    // B ldsm address (x2, lanes 0-15): n = nt*8 + (lane&7), col = kstep*16 + ((lane>>3)&1)*8
    const int b_nr  = lane & 7;
    const int b_c8  = ((lane >> 3) & 1) * 8;

    #pragma unroll
    for (int ks = 0; ks < 4; ks++) {
        uint32_t ah[4], al[4];
        uint32_t a_addr_h = smem_u32(xh + a_row * PADR + ks * 16 + a_c8);
        uint32_t a_addr_l = smem_u32(xl + a_row * PADR + ks * 16 + a_c8);
        ldsm_x4(a_addr_h, ah);
        ldsm_x4(a_addr_l, al);
        #pragma unroll
        for (int nt = 0; nt < 8; nt++) {
            uint32_t bh[2], bl[2];
            uint32_t b_off = (nt * 8 + b_nr) * PADR + ks * 16 + b_c8;
            ldsm_x2(smem_u32(wh + b_off), bh);
            ldsm_x2(smem_u32(wl + b_off), bl);
            mma_bf16(acc[nt], ah, bh);   // hi * hi
            mma_bf16(acc[nt], ah, bl);   // hi * lo
            mma_bf16(acc[nt], al, bh);   // lo * hi
        }
    }

    // epilogue: C fragment lane l=4g+t: c0=C[g][2t], c1=C[g][2t+1], c2=C[g+8][2t], c3=C[g+8][2t+1]
    const int g  = lane >> 2;
    const int t2 = (lane & 3) * 2;
    const int gn_a = n0 + m0 + g;
    const int gn_b = gn_a + 8;
    #pragma unroll
    for (int nt = 0; nt < 8; nt++) {
        int colh = k * 64 + nt * 8 + t2;
        if (gn_a < NN) {
            __half2 h = __floats2half2_rn(acc[nt][0], acc[nt][1]);
            *(__half2*)(g_xw + (size_t)gn_a * KROW + colh) = h;
        }
        if (gn_b < NN) {
            __half2 h = __floats2half2_rn(acc[nt][2], acc[nt][3]);
            *(__half2*)(g_xw + (size_t)gn_b * KROW + colh) = h;
        }
    }
}

// ---------------------------------------------------------------------------
// edge pass: gather 4 corners (fp16) from g_xw[col], blend, scatter-add
// ---------------------------------------------------------------------------
__global__ __launch_bounds__(256) void edge_kernel(const int*   __restrict__ ei,
                                                   const float* __restrict__ pseudo,
                                                   float*       __restrict__ out) {
    const int warp   = (blockIdx.x * blockDim.x + threadIdx.x) >> 5;
    const int lane   = threadIdx.x & 31;
    const int nwarps = (gridDim.x * blockDim.x) >> 5;

    for (int e = warp; e < EE; e += nwarps) {
        int row = ei[e];
        int col = ei[EE + e];
        float v0 = pseudo[2 * e]     * 4.0f;
        float v1 = pseudo[2 * e + 1] * 4.0f;
        float fl0 = floorf(v0), fl1 = floorf(v1);
        float f0 = v0 - fl0, f1 = v1 - fl1;
        int i0 = (int)fl0, i1 = (int)fl1;
        int i0p = i0 + 1; if (i0p >= 5) i0p -= 5;
        int i1p = i1 + 1; if (i1p >= 5) i1p -= 5;

        float g0 = 1.0f - f0, g1 = 1.0f - f1;
        float w00 = g0 * g1, w10 = f0 * g1, w01 = g0 * f1, w11 = f0 * f1;

        const __half2* base = (const __half2*)(g_xw + (size_t)col * KROW);
        int ia = (i0  * 5 + i1 ) * 32 + lane;
        int ib = (i0p * 5 + i1 ) * 32 + lane;
        int ic = (i0  * 5 + i1p) * 32 + lane;
        int id = (i0p * 5 + i1p) * 32 + lane;
        float2 a = __half22float2(base[ia]);
        float2 b = __half22float2(base[ib]);
        float2 c = __half22float2(base[ic]);
        float2 d = __half22float2(base[id]);

        float rx = w00 * a.x + w10 * b.x + w01 * c.x + w11 * d.x;
        float ry = w00 * a.y + w10 * b.y + w01 * c.y + w11 * d.y;

        float* op = out + (size_t)row * FOUT + lane * 2;
        asm volatile("red.global.add.v2.f32 [%0], {%1, %2};"
                     :: "l"(op), "f"(rx), "f"(ry) : "memory");
        if (lane == 0) atomicAdd(&g_deg[row], 1.0f);
    }
}

// ---------------------------------------------------------------------------
// final: out = out / max(deg,1) + x @ root + bias
// ---------------------------------------------------------------------------
__global__ __launch_bounds__(256) void final_kernel(const float* __restrict__ x,
                                                    const float* __restrict__ root,
                                                    const float* __restrict__ bias,
                                                    float*       __restrict__ out) {
    __shared__ float As[64][128];
    __shared__ float Rs[64][64];
    const int n0  = blockIdx.x * 128;
    const int tid = threadIdx.x;

    {
        const float4* src = (const float4*)root;
        float4* dst = (float4*)(&Rs[0][0]);
        #pragma unroll
        for (int j = 0; j < 4; j++) dst[j * 256 + tid] = src[j * 256 + tid];
    }
    #pragma unroll
    for (int it = 0; it < 8; it++) {
        int flat = it * 256 + tid;
        int n  = flat & 127;
        int i4 = flat >> 7;
        float4 v = make_float4(0.f, 0.f, 0.f, 0.f);
        int gn = n0 + n;
        if (gn < NN) v = *(const float4*)(x + (size_t)gn * 64 + i4 * 4);
        As[i4 * 4 + 0][n] = v.x;
        As[i4 * 4 + 1][n] = v.y;
        As[i4 * 4 + 2][n] = v.z;
        As[i4 * 4 + 3][n] = v.w;
    }
    __syncthreads();

    const int tx = tid & 7;
    const int ty = tid >> 3;
    float acc[4][8];
    #pragma unroll
    for (int m = 0; m < 4; m++)
        #pragma unroll
        for (int o = 0; o < 8; o++) acc[m][o] = 0.f;

    #pragma unroll 8
    for (int kk = 0; kk < 64; kk++) {
        float4 a  = *(const float4*)(&As[kk][ty * 4]);
        float4 b0 = *(const float4*)(&Rs[kk][tx * 8]);
        float4 b1 = *(const float4*)(&Rs[kk][tx * 8 + 4]);
        float av[4] = {a.x, a.y, a.z, a.w};
        float bv[8] = {b0.x, b0.y, b0.z, b0.w, b1.x, b1.y, b1.z, b1.w};
        #pragma unroll
        for (int m = 0; m < 4; m++)
            #pragma unroll
            for (int o = 0; o < 8; o++)
                acc[m][o] = fmaf(av[m], bv[o], acc[m][o]);
    }

    #pragma unroll
    for (int m = 0; m < 4; m++) {
        int gn = n0 + ty * 4 + m;
        if (gn < NN) {
            float scale = 1.0f / fmaxf(g_deg[gn], 1.0f);
            float* dst = out + (size_t)gn * 64 + tx * 8;
            #pragma unroll
            for (int o = 0; o < 8; o++) {
                dst[o] = dst[o] * scale + acc[m][o] + __ldg(bias + tx * 8 + o);
            }
        }
    }
}

// ---------------------------------------------------------------------------
extern "C" void kernel_launch(void* const* d_in, const int* in_sizes, int n_in,
                              void* d_out, int out_size) {
    const float* x      = (const float*)d_in[0];
    const int*   ei     = (const int*)  d_in[1];
    const float* pseudo = (const float*)d_in[2];
    const float* weight = (const float*)d_in[3];
    const float* root   = (const float*)d_in[4];
    const float* bias   = (const float*)d_in[5];
    float* out = (float*)d_out;

    static bool attr_done = false;
    const int smem_bytes = (128 * PADR * 2 + 64 * PADR * 2) * (int)sizeof(__nv_bfloat16);
    if (!attr_done) {
        cudaFuncSetAttribute(xw_mma, cudaFuncAttributeMaxDynamicSharedMemorySize, smem_bytes);
        attr_done = true;
    }

    prep_x<<<(NN * 64 + 255) / 256, 256>>>(x);
    prep_w<<<(KP * 64 * 64 + 255) / 256, 256>>>(weight);
    zero_kernel<<<(NN * FOUT + 255) / 256, 256>>>(out);

    dim3 g2((NN + 127) / 128, KP);
    xw_mma<<<g2, 256, smem_bytes>>>(nullptr);

    edge_kernel<<<4096, 256>>>(ei, pseudo, out);

    final_kernel<<<(NN + 127) / 128, 256>>>(x, root, bias, out);
}

// round 4
// speedup vs baseline: 2.1495x; 1.0835x over previous
#include <cuda_runtime.h>
#include <cuda_bf16.h>
#include <cuda_fp16.h>
#include <cstdint>

#define NN   50000
#define EE   1600000
#define KP   25
#define KG   5
#define FOUT 64
#define KROW (KP * FOUT)          // 1600

// ---------------- device scratch (no runtime allocation allowed) -----------
__device__ __nv_bfloat16 g_xhi[(size_t)NN * 64];
__device__ __nv_bfloat16 g_xlo[(size_t)NN * 64];
__device__ __nv_bfloat16 g_wthi[KP * 64 * 64];   // W^T: [k][o][i]
__device__ __nv_bfloat16 g_wtlo[KP * 64 * 64];
__device__ __half        g_xw[(size_t)NN * KROW];   // 160 MB fp16 table
__device__ float         g_deg[NN];

// ---------------- helpers ---------------------------------------------------
__device__ __forceinline__ uint32_t smem_u32(const void* p) {
    uint32_t a;
    asm("{ .reg .u64 t; cvta.to.shared.u64 t, %1; cvt.u32.u64 %0, t; }"
        : "=r"(a) : "l"(p));
    return a;
}
__device__ __forceinline__ void ldsm_x4(uint32_t addr, uint32_t* r) {
    asm volatile("ldmatrix.sync.aligned.m8n8.x4.shared.b16 {%0,%1,%2,%3}, [%4];"
                 : "=r"(r[0]), "=r"(r[1]), "=r"(r[2]), "=r"(r[3]) : "r"(addr));
}
__device__ __forceinline__ void mma_bf16(float* c, const uint32_t* a, const uint32_t* b) {
    asm volatile(
        "mma.sync.aligned.m16n8k16.row.col.f32.bf16.bf16.f32 "
        "{%0,%1,%2,%3}, {%4,%5,%6,%7}, {%8,%9}, {%0,%1,%2,%3};"
        : "+f"(c[0]), "+f"(c[1]), "+f"(c[2]), "+f"(c[3])
        : "r"(a[0]), "r"(a[1]), "r"(a[2]), "r"(a[3]), "r"(b[0]), "r"(b[1]));
}

// ---------------------------------------------------------------------------
// prep: split x into bf16 hi/lo, zero out + deg
// ---------------------------------------------------------------------------
__global__ void prep_x(const float* __restrict__ x, float* __restrict__ out) {
    int i = blockIdx.x * blockDim.x + threadIdx.x;
    if (i >= NN * 64) return;
    float v = x[i];
    __nv_bfloat16 h = __float2bfloat16(v);
    g_xhi[i] = h;
    g_xlo[i] = __float2bfloat16(v - __bfloat162float(h));
    out[i] = 0.0f;
    if (i < NN) g_deg[i] = 0.0f;
}
__global__ void prep_w(const float* __restrict__ w) {
    int i = blockIdx.x * blockDim.x + threadIdx.x;
    if (i >= KP * 64 * 64) return;
    int k = i >> 12, rem = i & 4095;
    int ii = rem >> 6, o = rem & 63;
    float v = w[i];
    __nv_bfloat16 h = __float2bfloat16(v);
    int dst = (k << 12) + (o << 6) + ii;     // [k][o][i]
    g_wthi[dst] = h;
    g_wtlo[dst] = __float2bfloat16(v - __bfloat162float(h));
}

// ---------------------------------------------------------------------------
// xw[n,k,:] = x[n,:] @ W[k]  via mma.sync bf16 hi/lo split (3 passes)
// Block: 256 threads, 128 nodes x KG=5 kernel slices. A fragments hoisted to
// registers once; per slice only W[k] is loaded (16 KB) and B LDSM'd via x4.
// ---------------------------------------------------------------------------
#define PADR 72   // row pad (bf16 elems): 144 B rows -> LDSM conflict-free

__global__ __launch_bounds__(256) void xw_mma() {
    extern __shared__ __nv_bfloat16 sm[];
    __nv_bfloat16* xh = sm;                       // [128][PADR]
    __nv_bfloat16* xl = xh + 128 * PADR;
    __nv_bfloat16* wh = xl + 128 * PADR;          // [64][PADR]
    __nv_bfloat16* wl = wh + 64 * PADR;

    const int tid  = threadIdx.x;
    const int wid  = tid >> 5;
    const int lane = tid & 31;
    const int n0   = blockIdx.x * 128;

    // ---- load x tile hi/lo (128 rows x 64 bf16)
    #pragma unroll
    for (int it = 0; it < 4; it++) {
        int flat = tid + 256 * it;
        int r = flat >> 3, j = flat & 7;
        int gn = n0 + r;
        uint4 vh = make_uint4(0, 0, 0, 0), vl = vh;
        if (gn < NN) {
            vh = *(const uint4*)(g_xhi + (size_t)gn * 64 + j * 8);
            vl = *(const uint4*)(g_xlo + (size_t)gn * 64 + j * 8);
        }
        *(uint4*)(xh + r * PADR + j * 8) = vh;
        *(uint4*)(xl + r * PADR + j * 8) = vl;
    }
    __syncthreads();

    // ---- hoist A fragments (16 rows per warp, all 64 k) into registers
    const int m0    = wid * 16;
    const int a_row = m0 + (lane & 15);
    const int a_c8  = (lane >> 4) * 8;
    uint32_t ah[4][4], al[4][4];
    #pragma unroll
    for (int ks = 0; ks < 4; ks++) {
        ldsm_x4(smem_u32(xh + a_row * PADR + ks * 16 + a_c8), ah[ks]);
        ldsm_x4(smem_u32(xl + a_row * PADR + ks * 16 + a_c8), al[ks]);
    }

    // B ldsm x4 lane mapping: r = lane&7 (matrix row), g = lane>>3 (which of 4 chunks)
    const int bw_r = lane & 7;
    const int bw_g = lane >> 3;

    const int g  = lane >> 2;
    const int t2 = (lane & 3) * 2;
    const int gn_a = n0 + m0 + g;
    const int gn_b = gn_a + 8;

    for (int j = 0; j < KG; j++) {
        const int k = blockIdx.y * KG + j;
        __syncthreads();   // protect W buffers from previous slice's readers
        // ---- load W^T[k] hi/lo (64 rows x 64 bf16)
        #pragma unroll
        for (int it = 0; it < 2; it++) {
            int flat = tid + 256 * it;
            int r = flat >> 3, jc = flat & 7;
            uint4 vh = *(const uint4*)(g_wthi + (k << 12) + r * 64 + jc * 8);
            uint4 vl = *(const uint4*)(g_wtlo + (k << 12) + r * 64 + jc * 8);
            *(uint4*)(wh + r * PADR + jc * 8) = vh;
            *(uint4*)(wl + r * PADR + jc * 8) = vl;
        }
        __syncthreads();

        #pragma unroll
        for (int nt = 0; nt < 8; nt++) {
            float acc[4] = {0.f, 0.f, 0.f, 0.f};
            uint32_t bh[8], bl[8];
            uint32_t row_off = (nt * 8 + bw_r) * PADR + bw_g * 8;
            ldsm_x4(smem_u32(wh + row_off), bh);          // chunks 0..3  (ks 0,1)
            ldsm_x4(smem_u32(wh + row_off + 32), bh + 4); // chunks 4..7  (ks 2,3)
            ldsm_x4(smem_u32(wl + row_off), bl);
            ldsm_x4(smem_u32(wl + row_off + 32), bl + 4);
            #pragma unroll
            for (int ks = 0; ks < 4; ks++) {
                mma_bf16(acc, ah[ks], bh + ks * 2);   // hi*hi
                mma_bf16(acc, ah[ks], bl + ks * 2);   // hi*lo
                mma_bf16(acc, al[ks], bh + ks * 2);   // lo*hi
            }
            // ---- epilogue for this 16x8 tile
            int colh = k * 64 + nt * 8 + t2;
            if (gn_a < NN) {
                __half2 h = __floats2half2_rn(acc[0], acc[1]);
                *(__half2*)(g_xw + (size_t)gn_a * KROW + colh) = h;
            }
            if (gn_b < NN) {
                __half2 h = __floats2half2_rn(acc[2], acc[3]);
                *(__half2*)(g_xw + (size_t)gn_b * KROW + colh) = h;
            }
        }
    }
}

// ---------------------------------------------------------------------------
// edge pass: 2 edges per warp-iteration; gather 4 fp16 corners each, blend,
// scatter-add with red.global.add.v2.f32
// ---------------------------------------------------------------------------
__global__ __launch_bounds__(256) void edge_kernel(const int*   __restrict__ ei,
                                                   const float* __restrict__ pseudo,
                                                   float*       __restrict__ out) {
    const int warp   = (blockIdx.x * blockDim.x + threadIdx.x) >> 5;
    const int lane   = threadIdx.x & 31;
    const int nwarps = (gridDim.x * blockDim.x) >> 5;

    for (int e = warp * 2; e < EE; e += nwarps * 2) {
        int2   rows = *(const int2*)(ei + e);
        int2   cols = *(const int2*)(ei + EE + e);
        float4 ps   = *(const float4*)(pseudo + 2 * e);

        // edge 0 indices
        float v0 = ps.x * 4.0f, v1 = ps.y * 4.0f;
        float fl0 = floorf(v0), fl1 = floorf(v1);
        float f0 = v0 - fl0, f1 = v1 - fl1;
        int i0 = (int)fl0, i1 = (int)fl1;
        int i0p = i0 + 1; if (i0p >= 5) i0p -= 5;
        int i1p = i1 + 1; if (i1p >= 5) i1p -= 5;
        // edge 1 indices
        float u0 = ps.z * 4.0f, u1 = ps.w * 4.0f;
        float gl0 = floorf(u0), gl1 = floorf(u1);
        float h0 = u0 - gl0, h1 = u1 - gl1;
        int j0 = (int)gl0, j1 = (int)gl1;
        int j0p = j0 + 1; if (j0p >= 5) j0p -= 5;
        int j1p = j1 + 1; if (j1p >= 5) j1p -= 5;

        const __half2* base0 = (const __half2*)(g_xw + (size_t)cols.x * KROW);
        const __half2* base1 = (const __half2*)(g_xw + (size_t)cols.y * KROW);
        // issue all 8 gathers before any math
        __half2 a0 = __ldg(base0 + (i0  * 5 + i1 ) * 32 + lane);
        __half2 b0 = __ldg(base0 + (i0p * 5 + i1 ) * 32 + lane);
        __half2 c0 = __ldg(base0 + (i0  * 5 + i1p) * 32 + lane);
        __half2 d0 = __ldg(base0 + (i0p * 5 + i1p) * 32 + lane);
        __half2 a1 = __ldg(base1 + (j0  * 5 + j1 ) * 32 + lane);
        __half2 b1 = __ldg(base1 + (j0p * 5 + j1 ) * 32 + lane);
        __half2 c1 = __ldg(base1 + (j0  * 5 + j1p) * 32 + lane);
        __half2 d1 = __ldg(base1 + (j0p * 5 + j1p) * 32 + lane);

        float g0 = 1.0f - f0, g1 = 1.0f - f1;
        float w00 = g0 * g1, w10 = f0 * g1, w01 = g0 * f1, w11 = f0 * f1;
        float2 A = __half22float2(a0), B = __half22float2(b0);
        float2 C = __half22float2(c0), D = __half22float2(d0);
        float rx = w00 * A.x + w10 * B.x + w01 * C.x + w11 * D.x;
        float ry = w00 * A.y + w10 * B.y + w01 * C.y + w11 * D.y;
        float* op0 = out + (size_t)rows.x * FOUT + lane * 2;
        asm volatile("red.global.add.v2.f32 [%0], {%1, %2};"
                     :: "l"(op0), "f"(rx), "f"(ry) : "memory");

        float q0 = 1.0f - h0, q1 = 1.0f - h1;
        float z00 = q0 * q1, z10 = h0 * q1, z01 = q0 * h1, z11 = h0 * h1;
        float2 A1 = __half22float2(a1), B1 = __half22float2(b1);
        float2 C1 = __half22float2(c1), D1 = __half22float2(d1);
        float sx = z00 * A1.x + z10 * B1.x + z01 * C1.x + z11 * D1.x;
        float sy = z00 * A1.y + z10 * B1.y + z01 * C1.y + z11 * D1.y;
        float* op1 = out + (size_t)rows.y * FOUT + lane * 2;
        asm volatile("red.global.add.v2.f32 [%0], {%1, %2};"
                     :: "l"(op1), "f"(sx), "f"(sy) : "memory");

        if (lane == 0) atomicAdd(&g_deg[rows.x], 1.0f);
        if (lane == 1) atomicAdd(&g_deg[rows.y], 1.0f);
    }
}

// ---------------------------------------------------------------------------
// final: out = out / max(deg,1) + x @ root + bias
// ---------------------------------------------------------------------------
__global__ __launch_bounds__(256) void final_kernel(const float* __restrict__ x,
                                                    const float* __restrict__ root,
                                                    const float* __restrict__ bias,
                                                    float*       __restrict__ out) {
    __shared__ float As[64][128];
    __shared__ float Rs[64][64];
    const int n0  = blockIdx.x * 128;
    const int tid = threadIdx.x;

    {
        const float4* src = (const float4*)root;
        float4* dst = (float4*)(&Rs[0][0]);
        #pragma unroll
        for (int j = 0; j < 4; j++) dst[j * 256 + tid] = src[j * 256 + tid];
    }
    #pragma unroll
    for (int it = 0; it < 8; it++) {
        int flat = it * 256 + tid;
        int n  = flat & 127;
        int i4 = flat >> 7;
        float4 v = make_float4(0.f, 0.f, 0.f, 0.f);
        int gn = n0 + n;
        if (gn < NN) v = *(const float4*)(x + (size_t)gn * 64 + i4 * 4);
        As[i4 * 4 + 0][n] = v.x;
        As[i4 * 4 + 1][n] = v.y;
        As[i4 * 4 + 2][n] = v.z;
        As[i4 * 4 + 3][n] = v.w;
    }
    __syncthreads();

    const int tx = tid & 7;
    const int ty = tid >> 3;
    float acc[4][8];
    #pragma unroll
    for (int m = 0; m < 4; m++)
        #pragma unroll
        for (int o = 0; o < 8; o++) acc[m][o] = 0.f;

    #pragma unroll 8
    for (int kk = 0; kk < 64; kk++) {
        float4 a  = *(const float4*)(&As[kk][ty * 4]);
        float4 b0 = *(const float4*)(&Rs[kk][tx * 8]);
        float4 b1 = *(const float4*)(&Rs[kk][tx * 8 + 4]);
        float av[4] = {a.x, a.y, a.z, a.w};
        float bv[8] = {b0.x, b0.y, b0.z, b0.w, b1.x, b1.y, b1.z, b1.w};
        #pragma unroll
        for (int m = 0; m < 4; m++)
            #pragma unroll
            for (int o = 0; o < 8; o++)
                acc[m][o] = fmaf(av[m], bv[o], acc[m][o]);
    }

    #pragma unroll
    for (int m = 0; m < 4; m++) {
        int gn = n0 + ty * 4 + m;
        if (gn < NN) {
            float scale = 1.0f / fmaxf(g_deg[gn], 1.0f);
            float* dst = out + (size_t)gn * 64 + tx * 8;
            #pragma unroll
            for (int o = 0; o < 8; o++) {
                dst[o] = dst[o] * scale + acc[m][o] + __ldg(bias + tx * 8 + o);
            }
        }
    }
}

// ---------------------------------------------------------------------------
extern "C" void kernel_launch(void* const* d_in, const int* in_sizes, int n_in,
                              void* d_out, int out_size) {
    const float* x      = (const float*)d_in[0];
    const int*   ei     = (const int*)  d_in[1];
    const float* pseudo = (const float*)d_in[2];
    const float* weight = (const float*)d_in[3];
    const float* root   = (const float*)d_in[4];
    const float* bias   = (const float*)d_in[5];
    float* out = (float*)d_out;

    const int smem_bytes = (128 * PADR * 2 + 64 * PADR * 2) * (int)sizeof(__nv_bfloat16);
    cudaFuncSetAttribute(xw_mma, cudaFuncAttributeMaxDynamicSharedMemorySize, smem_bytes);

    prep_x<<<(NN * 64 + 255) / 256, 256>>>(x, out);
    prep_w<<<(KP * 64 * 64 + 255) / 256, 256>>>(weight);

    dim3 g2((NN + 127) / 128, KP / KG);
    xw_mma<<<g2, 256, smem_bytes>>>();

    edge_kernel<<<6144, 256>>>(ei, pseudo, out);

    final_kernel<<<(NN + 127) / 128, 256>>>(x, root, bias, out);
}

// round 5
// speedup vs baseline: 2.3367x; 1.0871x over previous
#include <cuda_runtime.h>
#include <cuda_bf16.h>
#include <cuda_fp16.h>
#include <cstdint>

#define NN   50000
#define EE   1600000
#define KP   25
#define KG   5
#define FOUT 64
#define KROW (KP * FOUT)          // 1600

// ---------------- device scratch (no runtime allocation allowed) -----------
__device__ __nv_bfloat16 g_xhi[(size_t)NN * 64];
__device__ __nv_bfloat16 g_xlo[(size_t)NN * 64];
__device__ __nv_bfloat16 g_wthi[KP * 64 * 64];   // W^T: [k][o][i]
__device__ __nv_bfloat16 g_wtlo[KP * 64 * 64];
__device__ __half        g_xw[(size_t)NN * KROW];   // 160 MB fp16 table
__device__ float         g_deg[NN];
__device__ uint4         g_erec[EE];                // 25.6 MB edge records

// ---------------- helpers ---------------------------------------------------
__device__ __forceinline__ uint32_t smem_u32(const void* p) {
    uint32_t a;
    asm("{ .reg .u64 t; cvta.to.shared.u64 t, %1; cvt.u32.u64 %0, t; }"
        : "=r"(a) : "l"(p));
    return a;
}
__device__ __forceinline__ void ldsm_x4(uint32_t addr, uint32_t* r) {
    asm volatile("ldmatrix.sync.aligned.m8n8.x4.shared.b16 {%0,%1,%2,%3}, [%4];"
                 : "=r"(r[0]), "=r"(r[1]), "=r"(r[2]), "=r"(r[3]) : "r"(addr));
}
__device__ __forceinline__ void mma_bf16(float* c, const uint32_t* a, const uint32_t* b) {
    asm volatile(
        "mma.sync.aligned.m16n8k16.row.col.f32.bf16.bf16.f32 "
        "{%0,%1,%2,%3}, {%4,%5,%6,%7}, {%8,%9}, {%0,%1,%2,%3};"
        : "+f"(c[0]), "+f"(c[1]), "+f"(c[2]), "+f"(c[3])
        : "r"(a[0]), "r"(a[1]), "r"(a[2]), "r"(a[3]), "r"(b[0]), "r"(b[1]));
}

// ---------------------------------------------------------------------------
// prep: split x into bf16 hi/lo, zero out + deg
// ---------------------------------------------------------------------------
__global__ void prep_x(const float* __restrict__ x, float* __restrict__ out) {
    int i = blockIdx.x * blockDim.x + threadIdx.x;
    if (i >= NN * 64) return;
    float v = x[i];
    __nv_bfloat16 h = __float2bfloat16(v);
    g_xhi[i] = h;
    g_xlo[i] = __float2bfloat16(v - __bfloat162float(h));
    out[i] = 0.0f;
    if (i < NN) g_deg[i] = 0.0f;
}
__global__ void prep_w(const float* __restrict__ w) {
    int i = blockIdx.x * blockDim.x + threadIdx.x;
    if (i >= KP * 64 * 64) return;
    int k = i >> 12, rem = i & 4095;
    int ii = rem >> 6, o = rem & 63;
    float v = w[i];
    __nv_bfloat16 h = __float2bfloat16(v);
    int dst = (k << 12) + (o << 6) + ii;     // [k][o][i]
    g_wthi[dst] = h;
    g_wtlo[dst] = __float2bfloat16(v - __bfloat162float(h));
}

// ---------------------------------------------------------------------------
// prep_edges: one thread per edge; all scalar spline math + degree atomic.
// Record: {row*64, col*1600, packed cells (c, c+5, c+1, c+6), frac as half2}
// ---------------------------------------------------------------------------
__global__ __launch_bounds__(256) void prep_edges(const int* __restrict__ ei,
                                                  const float* __restrict__ ps) {
    int e = blockIdx.x * blockDim.x + threadIdx.x;
    if (e >= EE) return;
    int row = ei[e];
    int col = ei[EE + e];
    float2 p = *(const float2*)(ps + 2 * e);
    float v0 = p.x * 4.0f, v1 = p.y * 4.0f;
    float fl0 = floorf(v0), fl1 = floorf(v1);
    float f0 = v0 - fl0, f1 = v1 - fl1;
    int i0 = (int)fl0, i1 = (int)fl1;        // 0..3, +1 stays in range (no wrap)
    unsigned c00 = (unsigned)(i0 * 5 + i1);
    unsigned cells = c00 | ((c00 + 5u) << 8) | ((c00 + 1u) << 16) | ((c00 + 6u) << 24);
    __half2 fh = __floats2half2_rn(f0, f1);
    uint4 rec;
    rec.x = (unsigned)(row * FOUT);
    rec.y = (unsigned)(col * KROW);
    rec.z = cells;
    rec.w = *(unsigned*)&fh;
    g_erec[e] = rec;
    atomicAdd(&g_deg[row], 1.0f);
}

// ---------------------------------------------------------------------------
// xw[n,k,:] = x[n,:] @ W[k]  via mma.sync bf16 hi/lo split (3 passes)
// ---------------------------------------------------------------------------
#define PADR 72   // row pad (bf16 elems): 144 B rows -> LDSM conflict-free

__global__ __launch_bounds__(256) void xw_mma() {
    extern __shared__ __nv_bfloat16 sm[];
    __nv_bfloat16* xh = sm;                       // [128][PADR]
    __nv_bfloat16* xl = xh + 128 * PADR;
    __nv_bfloat16* wh = xl + 128 * PADR;          // [64][PADR]
    __nv_bfloat16* wl = wh + 64 * PADR;

    const int tid  = threadIdx.x;
    const int wid  = tid >> 5;
    const int lane = tid & 31;
    const int n0   = blockIdx.x * 128;

    #pragma unroll
    for (int it = 0; it < 4; it++) {
        int flat = tid + 256 * it;
        int r = flat >> 3, j = flat & 7;
        int gn = n0 + r;
        uint4 vh = make_uint4(0, 0, 0, 0), vl = vh;
        if (gn < NN) {
            vh = *(const uint4*)(g_xhi + (size_t)gn * 64 + j * 8);
            vl = *(const uint4*)(g_xlo + (size_t)gn * 64 + j * 8);
        }
        *(uint4*)(xh + r * PADR + j * 8) = vh;
        *(uint4*)(xl + r * PADR + j * 8) = vl;
    }
    __syncthreads();

    const int m0    = wid * 16;
    const int a_row = m0 + (lane & 15);
    const int a_c8  = (lane >> 4) * 8;
    uint32_t ah[4][4], al[4][4];
    #pragma unroll
    for (int ks = 0; ks < 4; ks++) {
        ldsm_x4(smem_u32(xh + a_row * PADR + ks * 16 + a_c8), ah[ks]);
        ldsm_x4(smem_u32(xl + a_row * PADR + ks * 16 + a_c8), al[ks]);
    }

    const int bw_r = lane & 7;
    const int bw_g = lane >> 3;
    const int g  = lane >> 2;
    const int t2 = (lane & 3) * 2;
    const int gn_a = n0 + m0 + g;
    const int gn_b = gn_a + 8;

    for (int j = 0; j < KG; j++) {
        const int k = blockIdx.y * KG + j;
        __syncthreads();
        #pragma unroll
        for (int it = 0; it < 2; it++) {
            int flat = tid + 256 * it;
            int r = flat >> 3, jc = flat & 7;
            uint4 vh = *(const uint4*)(g_wthi + (k << 12) + r * 64 + jc * 8);
            uint4 vl = *(const uint4*)(g_wtlo + (k << 12) + r * 64 + jc * 8);
            *(uint4*)(wh + r * PADR + jc * 8) = vh;
            *(uint4*)(wl + r * PADR + jc * 8) = vl;
        }
        __syncthreads();

        #pragma unroll
        for (int nt = 0; nt < 8; nt++) {
            float acc[4] = {0.f, 0.f, 0.f, 0.f};
            uint32_t bh[8], bl[8];
            uint32_t row_off = (nt * 8 + bw_r) * PADR + bw_g * 8;
            ldsm_x4(smem_u32(wh + row_off), bh);
            ldsm_x4(smem_u32(wh + row_off + 32), bh + 4);
            ldsm_x4(smem_u32(wl + row_off), bl);
            ldsm_x4(smem_u32(wl + row_off + 32), bl + 4);
            #pragma unroll
            for (int ks = 0; ks < 4; ks++) {
                mma_bf16(acc, ah[ks], bh + ks * 2);
                mma_bf16(acc, ah[ks], bl + ks * 2);
                mma_bf16(acc, al[ks], bh + ks * 2);
            }
            int colh = k * 64 + nt * 8 + t2;
            if (gn_a < NN) {
                __half2 h = __floats2half2_rn(acc[0], acc[1]);
                *(__half2*)(g_xw + (size_t)gn_a * KROW + colh) = h;
            }
            if (gn_b < NN) {
                __half2 h = __floats2half2_rn(acc[2], acc[3]);
                *(__half2*)(g_xw + (size_t)gn_b * KROW + colh) = h;
            }
        }
    }
}

// ---------------------------------------------------------------------------
// edge pass: record-driven. 2 edges per warp-iteration.
// ---------------------------------------------------------------------------
__global__ __launch_bounds__(256) void edge_kernel(float* __restrict__ out) {
    const int warp   = (blockIdx.x * blockDim.x + threadIdx.x) >> 5;
    const int lane2  = (threadIdx.x & 31) * 2;
    const int nwarps = (gridDim.x * blockDim.x) >> 5;

    for (int e = warp * 2; e < EE; e += nwarps * 2) {
        uint4 r0 = g_erec[e];
        uint4 r1 = g_erec[e + 1];

        const __half* p0 = g_xw + r0.y + lane2;
        const __half* p1 = g_xw + r1.y + lane2;
        unsigned c0 = r0.z, c1 = r1.z;

        __half2 A0 = *(const __half2*)(p0 + ((c0 & 255u) << 6));
        __half2 B0 = *(const __half2*)(p0 + (((c0 >> 8) & 255u) << 6));
        __half2 C0 = *(const __half2*)(p0 + (((c0 >> 16) & 255u) << 6));
        __half2 D0 = *(const __half2*)(p0 + ((c0 >> 24) << 6));
        __half2 A1 = *(const __half2*)(p1 + ((c1 & 255u) << 6));
        __half2 B1 = *(const __half2*)(p1 + (((c1 >> 8) & 255u) << 6));
        __half2 C1 = *(const __half2*)(p1 + (((c1 >> 16) & 255u) << 6));
        __half2 D1 = *(const __half2*)(p1 + ((c1 >> 24) << 6));

        // edge 0 blend
        {
            float2 f = __half22float2(*(const __half2*)&r0.w);
            float g0 = 1.0f - f.x, g1 = 1.0f - f.y;
            float w00 = g0 * g1, w10 = f.x * g1, w01 = g0 * f.y, w11 = f.x * f.y;
            float2 a = __half22float2(A0), b = __half22float2(B0);
            float2 c = __half22float2(C0), d = __half22float2(D0);
            float rx = w00 * a.x + w10 * b.x + w01 * c.x + w11 * d.x;
            float ry = w00 * a.y + w10 * b.y + w01 * c.y + w11 * d.y;
            float* op = out + r0.x + lane2;
            asm volatile("red.global.add.v2.f32 [%0], {%1, %2};"
                         :: "l"(op), "f"(rx), "f"(ry) : "memory");
        }
        // edge 1 blend
        {
            float2 f = __half22float2(*(const __half2*)&r1.w);
            float g0 = 1.0f - f.x, g1 = 1.0f - f.y;
            float w00 = g0 * g1, w10 = f.x * g1, w01 = g0 * f.y, w11 = f.x * f.y;
            float2 a = __half22float2(A1), b = __half22float2(B1);
            float2 c = __half22float2(C1), d = __half22float2(D1);
            float sx = w00 * a.x + w10 * b.x + w01 * c.x + w11 * d.x;
            float sy = w00 * a.y + w10 * b.y + w01 * c.y + w11 * d.y;
            float* op = out + r1.x + lane2;
            asm volatile("red.global.add.v2.f32 [%0], {%1, %2};"
                         :: "l"(op), "f"(sx), "f"(sy) : "memory");
        }
    }
}

// ---------------------------------------------------------------------------
// final: out = out / max(deg,1) + x @ root + bias
// ---------------------------------------------------------------------------
__global__ __launch_bounds__(256) void final_kernel(const float* __restrict__ x,
                                                    const float* __restrict__ root,
                                                    const float* __restrict__ bias,
                                                    float*       __restrict__ out) {
    __shared__ float As[64][128];
    __shared__ float Rs[64][64];
    const int n0  = blockIdx.x * 128;
    const int tid = threadIdx.x;

    {
        const float4* src = (const float4*)root;
        float4* dst = (float4*)(&Rs[0][0]);
        #pragma unroll
        for (int j = 0; j < 4; j++) dst[j * 256 + tid] = src[j * 256 + tid];
    }
    #pragma unroll
    for (int it = 0; it < 8; it++) {
        int flat = it * 256 + tid;
        int n  = flat & 127;
        int i4 = flat >> 7;
        float4 v = make_float4(0.f, 0.f, 0.f, 0.f);
        int gn = n0 + n;
        if (gn < NN) v = *(const float4*)(x + (size_t)gn * 64 + i4 * 4);
        As[i4 * 4 + 0][n] = v.x;
        As[i4 * 4 + 1][n] = v.y;
        As[i4 * 4 + 2][n] = v.z;
        As[i4 * 4 + 3][n] = v.w;
    }
    __syncthreads();

    const int tx = tid & 7;
    const int ty = tid >> 3;
    float acc[4][8];
    #pragma unroll
    for (int m = 0; m < 4; m++)
        #pragma unroll
        for (int o = 0; o < 8; o++) acc[m][o] = 0.f;

    #pragma unroll 8
    for (int kk = 0; kk < 64; kk++) {
        float4 a  = *(const float4*)(&As[kk][ty * 4]);
        float4 b0 = *(const float4*)(&Rs[kk][tx * 8]);
        float4 b1 = *(const float4*)(&Rs[kk][tx * 8 + 4]);
        float av[4] = {a.x, a.y, a.z, a.w};
        float bv[8] = {b0.x, b0.y, b0.z, b0.w, b1.x, b1.y, b1.z, b1.w};
        #pragma unroll
        for (int m = 0; m < 4; m++)
            #pragma unroll
            for (int o = 0; o < 8; o++)
                acc[m][o] = fmaf(av[m], bv[o], acc[m][o]);
    }

    #pragma unroll
    for (int m = 0; m < 4; m++) {
        int gn = n0 + ty * 4 + m;
        if (gn < NN) {
            float scale = 1.0f / fmaxf(g_deg[gn], 1.0f);
            float* dst = out + (size_t)gn * 64 + tx * 8;
            #pragma unroll
            for (int o = 0; o < 8; o++) {
                dst[o] = dst[o] * scale + acc[m][o] + __ldg(bias + tx * 8 + o);
            }
        }
    }
}

// ---------------------------------------------------------------------------
extern "C" void kernel_launch(void* const* d_in, const int* in_sizes, int n_in,
                              void* d_out, int out_size) {
    const float* x      = (const float*)d_in[0];
    const int*   ei     = (const int*)  d_in[1];
    const float* pseudo = (const float*)d_in[2];
    const float* weight = (const float*)d_in[3];
    const float* root   = (const float*)d_in[4];
    const float* bias   = (const float*)d_in[5];
    float* out = (float*)d_out;

    const int smem_bytes = (128 * PADR * 2 + 64 * PADR * 2) * (int)sizeof(__nv_bfloat16);
    cudaFuncSetAttribute(xw_mma, cudaFuncAttributeMaxDynamicSharedMemorySize, smem_bytes);

    prep_x<<<(NN * 64 + 255) / 256, 256>>>(x, out);
    prep_w<<<(KP * 64 * 64 + 255) / 256, 256>>>(weight);
    prep_edges<<<(EE + 255) / 256, 256>>>(ei, pseudo);

    dim3 g2((NN + 127) / 128, KP / KG);
    xw_mma<<<g2, 256, smem_bytes>>>();

    edge_kernel<<<6144, 256>>>(out);

    final_kernel<<<(NN + 127) / 128, 256>>>(x, root, bias, out);
}